// round 2
// baseline (speedup 1.0000x reference)
#include <cuda_runtime.h>
#include <math.h>

#define BB 4
#define LL 512
#define NTYPE 20
#define HH 6
#define DKK 10
#define DMM 60
#define EDD 59
#define NTH 256

// device scratch (no allocation allowed)
__device__ float g_q[BB*LL*DMM];        // q pre-scaled by 1/sqrt(DK)
__device__ float g_k[BB*LL*DMM];
__device__ float g_v[BB*LL*DMM];
// scrambled folded tables: [b][h(0..2)][e(0..2)][j][k], stores g=(j+2e)%3
__device__ float g_va3[BB*3*3*LL*DKK];
__device__ float g_vg3[BB*3*3*LL*DKK];

__global__ void prep_kernel(const float* __restrict__ ev,      // (B, L+1, 2)
                            const float* __restrict__ embed_w, // (ED, NT)
                            const float* __restrict__ q_w, const float* __restrict__ q_b,
                            const float* __restrict__ k_w, const float* __restrict__ k_b,
                            const float* __restrict__ v_w, const float* __restrict__ v_b,
                            const float* __restrict__ alpha_w, // (10, 30)
                            const float* __restrict__ gamma_w) // (10, 30)
{
    int row = blockIdx.x;           // b*L + j
    int b = row >> 9, j = row & (LL-1);
    __shared__ float feat[DMM];
    __shared__ float vrow[DMM];
    int t = threadIdx.x;
    const float* e = ev + (size_t)b*(LL+1)*2;
    if (t == 0) {
        float tprev = (j > 0) ? e[(j-1)*2] : 0.0f;
        feat[0] = e[j*2] - tprev;
    }
    int type = (int)e[j*2 + 1];
    if (t < EDD) feat[1+t] = embed_w[t*NTYPE + type];
    __syncthreads();
    if (t < DMM) {
        float sq = q_b[t], sk = k_b[t], sv = v_b[t];
        #pragma unroll
        for (int n = 0; n < DMM; n++) {
            float f = feat[n];
            sq += f * q_w[t*DMM + n];
            sk += f * k_w[t*DMM + n];
            sv += f * v_w[t*DMM + n];
        }
        g_q[(size_t)row*DMM + t] = sq * 0.31622776601683794f;  // 1/sqrt(10)
        g_k[(size_t)row*DMM + t] = sk;
        g_v[(size_t)row*DMM + t] = sv;
        vrow[t] = sv;
    }
    __syncthreads();
    if (t < 90) {
        int h = t / 30, e3 = (t / 10) % 3, k = t % 10;
        int g = (j + 2*e3) % 3;
        float sa = 0.f, sg = 0.f;
        #pragma unroll
        for (int d = 0; d < DKK; d++) {
            sa += vrow[h*DKK + d]       * alpha_w[k*30 + g*DKK + d];
            sg += vrow[(3+h)*DKK + d]   * gamma_w[k*30 + g*DKK + d];
        }
        size_t idx = ((((size_t)b*3 + h)*3 + e3)*LL + j)*DKK + k;
        g_va3[idx] = sa;
        g_vg3[idx] = sg;
    }
}

__device__ __forceinline__ float softplus_f(float x) {
    return fmaxf(x, 0.f) + __logf(1.f + __expf(-fabsf(x)));
}

// v_mu: standard (unscrambled) semantics. One block per (b, i).
__global__ __launch_bounds__(NTH)
void vmu_kernel(const float* __restrict__ mu_w,   // (10, 60)
                const float* __restrict__ mu_b,
                float* __restrict__ out)
{
    int row = blockIdx.x;
    int b = row >> 9, i = row & (LL-1);
    __shared__ float sp[HH*LL];
    __shared__ float qs[DMM];
    __shared__ float red[HH*8];
    __shared__ float hm[HH], hinv[HH];
    __shared__ float vm[4*DMM];
    int t = threadIdx.x;
    int warp = t >> 5, lane = t & 31;
    const unsigned FULL = 0xffffffffu;

    if (t < DMM) qs[t] = g_q[(size_t)row*DMM + t];
    __syncthreads();

    float pmax[HH];
    #pragma unroll
    for (int h = 0; h < HH; h++) pmax[h] = -1e30f;
    const float* kbase = g_k + (size_t)b*LL*DMM;
    for (int j = t; j <= i; j += NTH) {
        const float4* kr4 = reinterpret_cast<const float4*>(kbase + (size_t)j*DMM);
        float s[HH];
        #pragma unroll
        for (int h = 0; h < HH; h++) s[h] = 0.f;
        #pragma unroll
        for (int m4 = 0; m4 < DMM/4; m4++) {
            float4 kv = kr4[m4];
            int m = m4*4;
            s[(m+0)/DKK] += qs[m+0]*kv.x;
            s[(m+1)/DKK] += qs[m+1]*kv.y;
            s[(m+2)/DKK] += qs[m+2]*kv.z;
            s[(m+3)/DKK] += qs[m+3]*kv.w;
        }
        #pragma unroll
        for (int h = 0; h < HH; h++) {
            sp[h*LL + j] = s[h];
            pmax[h] = fmaxf(pmax[h], s[h]);
        }
    }
    #pragma unroll
    for (int h = 0; h < HH; h++)
        #pragma unroll
        for (int o = 16; o > 0; o >>= 1)
            pmax[h] = fmaxf(pmax[h], __shfl_xor_sync(FULL, pmax[h], o));
    if (lane == 0) {
        #pragma unroll
        for (int h = 0; h < HH; h++) red[h*8 + warp] = pmax[h];
    }
    __syncthreads();
    if (t < HH) {
        float mv = red[t*8];
        #pragma unroll
        for (int w = 1; w < 8; w++) mv = fmaxf(mv, red[t*8 + w]);
        hm[t] = mv;
    }
    __syncthreads();

    float psum[HH];
    #pragma unroll
    for (int h = 0; h < HH; h++) psum[h] = 0.f;
    for (int j = t; j <= i; j += NTH) {
        #pragma unroll
        for (int h = 0; h < HH; h++) {
            float eV = __expf(sp[h*LL + j] - hm[h]);
            sp[h*LL + j] = eV;
            psum[h] += eV;
        }
    }
    #pragma unroll
    for (int h = 0; h < HH; h++)
        #pragma unroll
        for (int o = 16; o > 0; o >>= 1)
            psum[h] += __shfl_xor_sync(FULL, psum[h], o);
    __syncthreads();
    if (lane == 0) {
        #pragma unroll
        for (int h = 0; h < HH; h++) red[h*8 + warp] = psum[h];
    }
    __syncthreads();
    if (t < HH) {
        float sv = 0.f;
        #pragma unroll
        for (int w = 0; w < 8; w++) sv += red[t*8 + w];
        hinv[t] = 1.0f / sv;
    }
    __syncthreads();

    const float* vbase = g_v + (size_t)b*LL*DMM;
    if (t < 240) {
        int m = t % DMM;
        int part = t / DMM;
        int h = m / DKK;
        float acc = 0.f;
        for (int j = part; j <= i; j += 4)
            acc += sp[h*LL + j] * vbase[(size_t)j*DMM + m];
        vm[part*DMM + m] = acc * hinv[h];
    }
    __syncthreads();
    if (t < DKK) {
        float s = mu_b[t];
        #pragma unroll
        for (int m = 0; m < DMM; m++) {
            float pre = vm[m] + vm[DMM + m] + vm[2*DMM + m] + vm[3*DMM + m];
            s += pre * mu_w[t*DMM + m];
        }
        out[(size_t)row*DKK + t] = 1.0f / (1.0f + __expf(-s));
    }
}

// Big output kernel: one block per output row (b, i').
// Needs 6 attention rows: flattened R = 3i'+e (e=0..2):
//   alpha: head hA=R/512, query q=R%512;  gamma: head 3+hA, same query.
__global__ __launch_bounds__(NTH)
void big_kernel(const float* __restrict__ alpha_b,
                const float* __restrict__ gamma_b,
                float* __restrict__ out)
{
    int row = blockIdx.x;
    int b = row >> 9, ip = row & (LL-1);
    __shared__ float pa[3*LL];
    __shared__ float pg[3*LL];
    __shared__ float qa[3][DKK], qg[3][DKK];
    __shared__ float red[6*8];
    __shared__ float rmax[6], rinv[6];
    __shared__ float ab[DKK], gb[DKK];
    int t = threadIdx.x;
    int warp = t >> 5, lane = t & 31;
    const unsigned FULL = 0xffffffffu;

    int qe[3], he[3];
    #pragma unroll
    for (int e = 0; e < 3; e++) {
        int R = 3*ip + e;
        qe[e] = R & (LL-1);
        he[e] = R >> 9;             // 0..2
    }

    if (t < DKK) { ab[t] = alpha_b[t]; gb[t] = gamma_b[t]; }
    if (t < 30) {
        int e = t / DKK, d = t % DKK;
        const float* qrow = g_q + ((size_t)b*LL + qe[e])*DMM;
        qa[e][d] = qrow[he[e]*DKK + d];
        qg[e][d] = qrow[(3+he[e])*DKK + d];
    }
    __syncthreads();

    // ---- scores for 6 rows ----
    float mA[3], mG[3];
    #pragma unroll
    for (int e = 0; e < 3; e++) { mA[e] = -1e30f; mG[e] = -1e30f; }
    const float* kbase = g_k + (size_t)b*LL*DMM;
    bool sameh = (he[0] == he[2]);
    for (int j = t; j < LL; j += NTH) {
        float sA[3], sG[3];
        if (sameh) {
            int h = he[0];
            const float2* pka = (const float2*)(kbase + (size_t)j*DMM + h*DKK);
            const float2* pkg = (const float2*)(kbase + (size_t)j*DMM + (3+h)*DKK);
            float ka[DKK], kg[DKK];
            #pragma unroll
            for (int d2 = 0; d2 < 5; d2++) {
                float2 a2 = pka[d2], g2 = pkg[d2];
                ka[2*d2] = a2.x; ka[2*d2+1] = a2.y;
                kg[2*d2] = g2.x; kg[2*d2+1] = g2.y;
            }
            #pragma unroll
            for (int e = 0; e < 3; e++) {
                float a = 0.f, g = 0.f;
                #pragma unroll
                for (int d = 0; d < DKK; d++) { a += qa[e][d]*ka[d]; g += qg[e][d]*kg[d]; }
                sA[e] = a; sG[e] = g;
            }
        } else {
            float kr[DMM];
            const float4* kr4 = (const float4*)(kbase + (size_t)j*DMM);
            #pragma unroll
            for (int m4 = 0; m4 < DMM/4; m4++) {
                float4 kv = kr4[m4];
                kr[4*m4] = kv.x; kr[4*m4+1] = kv.y; kr[4*m4+2] = kv.z; kr[4*m4+3] = kv.w;
            }
            #pragma unroll
            for (int e = 0; e < 3; e++) {
                float a = 0.f, g = 0.f;
                #pragma unroll
                for (int d = 0; d < DKK; d++) {
                    a += qa[e][d]*kr[he[e]*DKK + d];
                    g += qg[e][d]*kr[(3+he[e])*DKK + d];
                }
                sA[e] = a; sG[e] = g;
            }
        }
        #pragma unroll
        for (int e = 0; e < 3; e++) {
            pa[e*LL + j] = sA[e];
            pg[e*LL + j] = sG[e];
            if (j <= qe[e]) {
                mA[e] = fmaxf(mA[e], sA[e]);
                mG[e] = fmaxf(mG[e], sG[e]);
            }
        }
    }
    // reduce maxima for 6 rows (r=0..2 alpha, 3..5 gamma)
    #pragma unroll
    for (int e = 0; e < 3; e++)
        #pragma unroll
        for (int o = 16; o > 0; o >>= 1) {
            mA[e] = fmaxf(mA[e], __shfl_xor_sync(FULL, mA[e], o));
            mG[e] = fmaxf(mG[e], __shfl_xor_sync(FULL, mG[e], o));
        }
    if (lane == 0) {
        #pragma unroll
        for (int e = 0; e < 3; e++) { red[e*8 + warp] = mA[e]; red[(3+e)*8 + warp] = mG[e]; }
    }
    __syncthreads();
    if (t < 6) {
        float mv = red[t*8];
        #pragma unroll
        for (int w = 1; w < 8; w++) mv = fmaxf(mv, red[t*8 + w]);
        rmax[t] = mv;
    }
    __syncthreads();

    // exp + sum
    float smA[3], smG[3];
    #pragma unroll
    for (int e = 0; e < 3; e++) { smA[e] = 0.f; smG[e] = 0.f; }
    for (int j = t; j < LL; j += NTH) {
        #pragma unroll
        for (int e = 0; e < 3; e++) {
            float va = 0.f, vg = 0.f;
            if (j <= qe[e]) {
                va = __expf(pa[e*LL + j] - rmax[e]);
                vg = __expf(pg[e*LL + j] - rmax[3+e]);
            }
            pa[e*LL + j] = va;  smA[e] += va;
            pg[e*LL + j] = vg;  smG[e] += vg;
        }
    }
    #pragma unroll
    for (int e = 0; e < 3; e++)
        #pragma unroll
        for (int o = 16; o > 0; o >>= 1) {
            smA[e] += __shfl_xor_sync(FULL, smA[e], o);
            smG[e] += __shfl_xor_sync(FULL, smG[e], o);
        }
    __syncthreads();
    if (lane == 0) {
        #pragma unroll
        for (int e = 0; e < 3; e++) { red[e*8 + warp] = smA[e]; red[(3+e)*8 + warp] = smG[e]; }
    }
    __syncthreads();
    if (t < 6) {
        float sv = 0.f;
        #pragma unroll
        for (int w = 0; w < 8; w++) sv += red[t*8 + w];
        rinv[t] = 1.0f / sv;
    }
    __syncthreads();
    for (int j = t; j < LL; j += NTH) {
        #pragma unroll
        for (int e = 0; e < 3; e++) {
            pa[e*LL + j] *= rinv[e];
            pg[e*LL + j] *= rinv[3+e];
        }
    }
    __syncthreads();

    // ---- fused output: v_alpha / v_gamma ----
    // addr(e,u,k) = offX[e] + u*10 + k, where offX[e] = ((b*3+he)*3+e)*5120 - e*5120
    int offA[3], offG[3];
    #pragma unroll
    for (int e = 0; e < 3; e++) {
        offA[e] = (((b*3 + he[e])*3 + e)*LL)*DKK - e*LL*DKK;
        offG[e] = offA[e];
    }
    size_t baseA = (size_t)BB*LL*DKK + (size_t)row*LL*DKK;
    size_t baseG = baseA + (size_t)BB*LL*LL*DKK;
    for (int f = t; f < LL*DKK; f += NTH) {
        int jp = f / DKK, k = f - jp*DKK;
        float A = 0.f, G = 0.f;
        if (jp <= ip) {
            A = ab[k]; G = gb[k];
            #pragma unroll
            for (int m = 0; m < 3; m++) {
                int u = 3*jp + m;
                int e = u >> 9;
                A += pa[u] * g_va3[offA[e] + u*DKK + k];
                G += pg[u] * g_vg3[offG[e] + u*DKK + k];
            }
            A = softplus_f(A);
            G = 0.1f * softplus_f(10.0f * G);
        }
        out[baseA + f] = A;
        out[baseG + f] = G;
    }
}

extern "C" void kernel_launch(void* const* d_in, const int* in_sizes, int n_in,
                              void* d_out, int out_size) {
    const float* ev      = (const float*)d_in[0];
    // d_in[1] = src_mask (deterministic tril) — recomputed as j<=i
    const float* embed_w = (const float*)d_in[2];
    const float* q_w     = (const float*)d_in[3];
    const float* q_b     = (const float*)d_in[4];
    const float* k_w     = (const float*)d_in[5];
    const float* k_b     = (const float*)d_in[6];
    const float* v_w     = (const float*)d_in[7];
    const float* v_b     = (const float*)d_in[8];
    const float* alpha_w = (const float*)d_in[9];
    const float* alpha_b = (const float*)d_in[10];
    const float* gamma_w = (const float*)d_in[11];
    const float* gamma_b = (const float*)d_in[12];
    const float* mu_w    = (const float*)d_in[13];
    const float* mu_b    = (const float*)d_in[14];
    float* out = (float*)d_out;

    prep_kernel<<<BB*LL, 128>>>(ev, embed_w, q_w, q_b, k_w, k_b, v_w, v_b, alpha_w, gamma_w);
    vmu_kernel<<<BB*LL, NTH>>>(mu_w, mu_b, out);
    big_kernel<<<BB*LL, NTH>>>(alpha_b, gamma_b, out);
}

// round 4
// speedup vs baseline: 1.4089x; 1.4089x over previous
#include <cuda_runtime.h>

#define BB 4
#define LL 512
#define NTYPE 20
#define HH 6
#define DKK 10
#define DMM 60
#define EDD 59

// device scratch (no allocation allowed)
__device__ float g_q[BB*LL*DMM];        // q pre-scaled by 1/sqrt(DK)
__device__ float g_k[BB*LL*DMM];
__device__ float g_v[BB*LL*DMM];
__device__ float g_va3[BB*3*3*LL*DKK];  // scrambled folded tables
__device__ float g_vg3[BB*3*3*LL*DKK];
__device__ float g_p[BB*HH*LL*LL];      // masked UNnormalized exp rows [b][h][q][j]
__device__ float g_scale[BB*HH*LL];     // 1/rowsum
__device__ float g_vmu[BB*LL*DMM];      // normalized (p@v), head-concat per (b,q)

// ---------------- K1: prep (16 rows/block, smem-staged weights) ----------------
__global__ __launch_bounds__(256)
void prep_kernel(const float* __restrict__ ev, const float* __restrict__ embed_w,
                 const float* __restrict__ q_w, const float* __restrict__ q_b,
                 const float* __restrict__ k_w, const float* __restrict__ k_b,
                 const float* __restrict__ v_w, const float* __restrict__ v_b,
                 const float* __restrict__ alpha_w, const float* __restrict__ gamma_w)
{
    __shared__ float wq[3600], wk[3600], wv[3600];   // transposed [n][m]
    __shared__ float wa[300], wg[300];               // transposed [c][k]
    __shared__ float feat[16][DMM];
    __shared__ float vr[16][DMM];
    __shared__ int   tys[16];
    int t = threadIdx.x;
    int row0 = blockIdx.x * 16;
    int b = row0 >> 9, j0 = row0 & (LL-1);
    const float* e = ev + (size_t)b*(LL+1)*2;

    if (t < 16) {
        int j = j0 + t;
        float tprev = (j > 0) ? e[(j-1)*2] : 0.0f;
        feat[t][0] = e[j*2] - tprev;
        tys[t] = (int)e[j*2 + 1];
    }
    for (int i = t; i < 3600; i += 256) {
        int m = i / 60, n = i - m*60;
        wq[n*60+m] = q_w[i]; wk[n*60+m] = k_w[i]; wv[n*60+m] = v_w[i];
    }
    for (int i = t; i < 300; i += 256) {
        int k = i / 30, c = i - k*30;
        wa[c*10 + k] = alpha_w[i]; wg[c*10 + k] = gamma_w[i];
    }
    __syncthreads();
    for (int i = t; i < 16*EDD; i += 256) {
        int r = i / EDD, m = i - r*EDD;
        feat[r][1+m] = embed_w[m*NTYPE + tys[r]];
    }
    __syncthreads();
    for (int i = t; i < 960; i += 256) {
        int r = i / 60, m = i - r*60;
        float sq = q_b[m], sk = k_b[m], sv = v_b[m];
        #pragma unroll
        for (int n = 0; n < 60; n++) {
            float fv = feat[r][n];
            sq += fv * wq[n*60+m];
            sk += fv * wk[n*60+m];
            sv += fv * wv[n*60+m];
        }
        int gi = (row0 + r)*60 + m;
        g_q[gi] = sq * 0.31622776601683794f;
        g_k[gi] = sk;
        g_v[gi] = sv;
        vr[r][m] = sv;
    }
    __syncthreads();
    for (int i = t; i < 1440; i += 256) {
        int r = i / 90, rem = i - r*90;
        int h = rem / 30, e3 = (rem / 10) % 3, k = rem % 10;
        int j = j0 + r;
        int g = (j + 2*e3) % 3;
        float sa = 0.f, sg = 0.f;
        #pragma unroll
        for (int d = 0; d < 10; d++) {
            sa += vr[r][h*10 + d]      * wa[(g*10+d)*10 + k];
            sg += vr[r][30 + h*10 + d] * wg[(g*10+d)*10 + k];
        }
        int idx = (((b*3 + h)*3 + e3)*LL + j)*DKK + k;
        g_va3[idx] = sa;
        g_vg3[idx] = sg;
    }
}

// ---------------- K2: attention rows (exp, rowsum, p@v) ----------------
// block = (b, h, qc 0..7); q-stripe: q = 8*li + qc, li=0..63. warp handles q-pairs.
__global__ __launch_bounds__(256)
void attn_kernel()
{
    int bx = blockIdx.x;
    int qc = bx & 7, bh = bx >> 3;
    int h = bh % 6, b = bh / 6;
    __shared__ float ks[LL*DKK], vs_[LL*DKK], qs[64*DKK];
    int t = threadIdx.x;
    const float* kg = g_k + (size_t)(b*LL)*DMM + h*DKK;
    const float* vg = g_v + (size_t)(b*LL)*DMM + h*DKK;
    const float* qg = g_q + (size_t)(b*LL)*DMM + h*DKK;
    for (int i = t; i < 2560; i += 256) {
        int j = i / 5, d2 = i - j*5;
        ((float2*)ks)[j*5 + d2]  = *(const float2*)(kg + (size_t)j*DMM + d2*2);
        ((float2*)vs_)[j*5 + d2] = *(const float2*)(vg + (size_t)j*DMM + d2*2);
    }
    for (int i = t; i < 320; i += 256) {
        int li = i / 5, d2 = i - li*5;
        int q = 8*li + qc;
        ((float2*)qs)[li*5 + d2] = *(const float2*)(qg + (size_t)q*DMM + d2*2);
    }
    __syncthreads();
    int w = t >> 5, lane = t & 31;
    const unsigned FULL = 0xffffffffu;
    for (int p = 0; p < 4; p++) {
        int li0 = w*8 + p*2, li1 = li0 + 1;
        int q0 = 8*li0 + qc, q1 = 8*li1 + qc;   // q1 = q0 + 8
        float q0r[10], q1r[10];
        #pragma unroll
        for (int d = 0; d < 10; d++) { q0r[d] = qs[li0*10+d]; q1r[d] = qs[li1*10+d]; }
        float sum0 = 0.f, sum1 = 0.f;
        float vm0[10], vm1[10];
        #pragma unroll
        for (int d = 0; d < 10; d++) { vm0[d] = 0.f; vm1[d] = 0.f; }
        int row0 = (b*HH + h)*LL + q0;
        int row1 = row0 + 8;
        float* p0 = g_p + (size_t)row0*LL;
        float* p1 = g_p + (size_t)row1*LL;
        for (int j = lane; j < LL; j += 32) {
            float e0 = 0.f, e1 = 0.f;
            if (j <= q1) {
                float kd[10], vd[10];
                #pragma unroll
                for (int d2 = 0; d2 < 5; d2++) {
                    float2 kk = ((float2*)ks)[j*5 + d2];
                    float2 vv = ((float2*)vs_)[j*5 + d2];
                    kd[2*d2] = kk.x; kd[2*d2+1] = kk.y;
                    vd[2*d2] = vv.x; vd[2*d2+1] = vv.y;
                }
                float s1 = 0.f;
                #pragma unroll
                for (int d = 0; d < 10; d++) s1 += q1r[d]*kd[d];
                e1 = __expf(s1);
                sum1 += e1;
                #pragma unroll
                for (int d = 0; d < 10; d++) vm1[d] += e1*vd[d];
                if (j <= q0) {
                    float s0 = 0.f;
                    #pragma unroll
                    for (int d = 0; d < 10; d++) s0 += q0r[d]*kd[d];
                    e0 = __expf(s0);
                    sum0 += e0;
                    #pragma unroll
                    for (int d = 0; d < 10; d++) vm0[d] += e0*vd[d];
                }
            }
            p0[j] = e0;
            p1[j] = e1;
        }
        #pragma unroll
        for (int o = 16; o > 0; o >>= 1) {
            sum0 += __shfl_xor_sync(FULL, sum0, o);
            sum1 += __shfl_xor_sync(FULL, sum1, o);
            #pragma unroll
            for (int d = 0; d < 10; d++) {
                vm0[d] += __shfl_xor_sync(FULL, vm0[d], o);
                vm1[d] += __shfl_xor_sync(FULL, vm1[d], o);
            }
        }
        if (lane == 0) {
            float i0 = 1.0f / sum0, i1 = 1.0f / sum1;
            g_scale[row0] = i0;
            g_scale[row1] = i1;
            float* o0 = g_vmu + ((size_t)(b*LL + q0))*DMM + h*DKK;
            float* o1 = g_vmu + ((size_t)(b*LL + q1))*DMM + h*DKK;
            #pragma unroll
            for (int d = 0; d < 10; d++) { o0[d] = vm0[d]*i0; o1[d] = vm1[d]*i1; }
        }
    }
}

// ---------------- K3: v_mu final sigmoid GEMV ----------------
__global__ __launch_bounds__(256)
void vmu_final(const float* __restrict__ mu_w, const float* __restrict__ mu_b,
               float* __restrict__ out)
{
    int idx = blockIdx.x*256 + threadIdx.x;
    if (idx >= BB*LL*DKK) return;
    int row = idx / DKK, k = idx - row*DKK;
    float s = mu_b[k];
    const float* pre = g_vmu + (size_t)row*DMM;
    #pragma unroll
    for (int m = 0; m < DMM; m++) s += pre[m] * __ldg(mu_w + k*DMM + m);
    out[idx] = 1.0f / (1.0f + __expf(-s));
}

__device__ __forceinline__ float softplus_f(float x) {
    return fmaxf(x, 0.f) + __logf(1.f + __expf(-fabsf(x)));
}

// ---------------- K4: fused softplus output, 4 rows/block ----------------
__global__ __launch_bounds__(256)
void big_kernel(const float* __restrict__ alpha_b,
                const float* __restrict__ gamma_b,
                float* __restrict__ out)
{
    int bx = blockIdx.x;                 // 512 blocks
    int b = bx >> 7, ip0 = (bx & 127) * 4;
    __shared__ float pa[12*LL], pg[12*LL];    // 48KB
    __shared__ float ab[DKK], gb[DKK];
    __shared__ int   rowAs[12], rowGs[12];
    __shared__ float scAs[12], scGs[12];
    int t = threadIdx.x;
    if (t < DKK) { ab[t] = alpha_b[t]; gb[t] = gamma_b[t]; }
    if (t < 12) {
        int R = 3*ip0 + t;
        int hA = R >> 9, q = R & (LL-1);
        int ra = (b*HH + hA)*LL + q;
        int rg = (b*HH + 3 + hA)*LL + q;
        rowAs[t] = ra; scAs[t] = g_scale[ra];
        rowGs[t] = rg; scGs[t] = g_scale[rg];
    }
    __syncthreads();
    for (int idx = t; idx < 12*128; idx += 256) {
        int r = idx >> 7, j4 = idx & 127;
        float4 va = ((const float4*)(g_p + (size_t)rowAs[r]*LL))[j4];
        float4 vg = ((const float4*)(g_p + (size_t)rowGs[r]*LL))[j4];
        float sa = scAs[r], sg = scGs[r];
        va.x *= sa; va.y *= sa; va.z *= sa; va.w *= sa;
        vg.x *= sg; vg.y *= sg; vg.z *= sg; vg.w *= sg;
        ((float4*)pa)[idx] = va;
        ((float4*)pg)[idx] = vg;
    }
    __syncthreads();

    for (int ipi = 0; ipi < 4; ipi++) {
        int ip = ip0 + ipi;
        size_t baseA = (size_t)BB*LL*DKK + ((size_t)(b*LL + ip))*(LL*DKK);
        size_t baseG = baseA + (size_t)BB*LL*LL*DKK;
        int tabb[3];
        #pragma unroll
        for (int e = 0; e < 3; e++) {
            int R = 3*ip + e;
            int hh = R >> 9;
            tabb[e] = ((b*3 + hh)*3 + e) * (LL*DKK);
        }
        int pbase = ipi * 1536;
        for (int f4 = t; f4 < 1280; f4 += 256) {
            int f = f4 * 4;
            float4 A4, G4;
            float* Ac = (float*)&A4;
            float* Gc = (float*)&G4;
            #pragma unroll
            for (int c = 0; c < 4; c++) {
                int fe = f + c;
                int jp = fe / 10, k = fe - jp*10;
                float A = 0.f, G = 0.f;
                if (jp <= ip) {
                    A = ab[k]; G = gb[k];
                    #pragma unroll
                    for (int m = 0; m < 3; m++) {
                        int u = 3*jp + m;
                        int e = u >> 9, j = u & (LL-1);
                        int ti = tabb[e] + j*10 + k;
                        A += pa[pbase + u] * g_va3[ti];
                        G += pg[pbase + u] * g_vg3[ti];
                    }
                    A = softplus_f(A);
                    G = 0.1f * softplus_f(10.0f * G);
                }
                Ac[c] = A; Gc[c] = G;
            }
            *(float4*)(out + baseA + f) = A4;
            *(float4*)(out + baseG + f) = G4;
        }
    }
}

extern "C" void kernel_launch(void* const* d_in, const int* in_sizes, int n_in,
                              void* d_out, int out_size) {
    const float* ev      = (const float*)d_in[0];
    // d_in[1] = src_mask (deterministic tril) — recomputed as j<=i
    const float* embed_w = (const float*)d_in[2];
    const float* q_w     = (const float*)d_in[3];
    const float* q_b     = (const float*)d_in[4];
    const float* k_w     = (const float*)d_in[5];
    const float* k_b     = (const float*)d_in[6];
    const float* v_w     = (const float*)d_in[7];
    const float* v_b     = (const float*)d_in[8];
    const float* alpha_w = (const float*)d_in[9];
    const float* alpha_b = (const float*)d_in[10];
    const float* gamma_w = (const float*)d_in[11];
    const float* gamma_b = (const float*)d_in[12];
    const float* mu_w    = (const float*)d_in[13];
    const float* mu_b    = (const float*)d_in[14];
    float* out = (float*)d_out;

    prep_kernel<<<128, 256>>>(ev, embed_w, q_w, q_b, k_w, k_b, v_w, v_b, alpha_w, gamma_w);
    attn_kernel<<<BB*HH*8, 256>>>();
    vmu_final<<<(BB*LL*DKK + 255)/256, 256>>>(mu_w, mu_b, out);
    big_kernel<<<512, 256>>>(alpha_b, gamma_b, out);
}